// round 9
// baseline (speedup 1.0000x reference)
#include <cuda_runtime.h>
#include <cuda_bf16.h>

// out[n,c,k,l] = x[n,c,oh,ow] - xpad[n,c,oh+i,ow+j]; K=7, PAD=3
// x:(16,64,56,56) f32 -> out:(16,64,49,3136) f32.
// Store-bound at the chip write-path ceiling (~6.7 TB/s effective).
//
// R8: staging latency hiding — all staging LDG.128 issued back-to-back
// (MLP=4/thread), halo zeroing executes inside the LDG shadow, then STS +
// one barrier. Store loop identical to the 96.1us best.

#define PLANE   3136        // 56*56
#define TPITCH  64          // padded pitch (16B-aligned rows)
#define TROWS   62          // 56 + 2*3
#define NTHREADS 256
#define NGROUPS 784         // 3136 / 4 float4-groups per k

__global__ __launch_bounds__(NTHREADS, 1)
void Subtraction_68212670595965_kernel(const float* __restrict__ x,
                                       float* __restrict__ out) {
    __shared__ float tile[TROWS * TPITCH];   // 62*64*4 = 15872 B

    const int nc = blockIdx.x;               // n*64 + c, 0..1023
    const float* __restrict__ xin = x + (size_t)nc * PLANE;
    float* __restrict__ outb = out + (size_t)nc * 49 * PLANE;

    const int tid = threadIdx.x;

    // ---- Staging, latency-hidden ----
    // (1) Issue all input loads first: 784 float4 over 256 threads -> 4
    //     predicated LDG.128 per thread, issued back-to-back (MLP=4).
    float4 v[4];
    int    dsts[4];
    #pragma unroll
    for (int it = 0; it < 4; ++it) {
        const int idx = tid + it * NTHREADS;     // 0..1023, valid < 784
        const bool ok = idx < 56 * 14;
        const int r  = idx / 14;                 // input row
        const int c4 = idx - r * 14;             // float4 within row
        dsts[it] = (r + 3) * TPITCH + 3 + c4 * 4;
        if (ok) v[it] = reinterpret_cast<const float4*>(xin + r * 56)[c4];
        else    { v[it] = make_float4(0.f, 0.f, 0.f, 0.f); dsts[it] = -1; }
    }

    // (2) Halo zeroing inside the LDG shadow.
    {
        float4 z = {0.f, 0.f, 0.f, 0.f};
        // top rows 0..2, bottom rows 59..61: 6*16 = 96 float4
        if (tid < 96) {
            const int half = tid / 48;               // 0=top, 1=bottom
            const int q    = tid - half * 48;        // 0..47
            const int row  = half ? (59 + q / 16) : (q / 16);
            reinterpret_cast<float4*>(&tile[row * TPITCH])[q & 15] = z;
        }
        // side halos: 56 rows x 8 cols (0..2, 59..63)
        #pragma unroll 1
        for (int s = tid; s < 448; s += NTHREADS) {
            const int r  = s / 8;
            const int cc = s & 7;
            const int col = (cc < 3) ? cc : (56 + cc);
            tile[(r + 3) * TPITCH + col] = 0.0f;
        }
    }

    // (3) Commit loaded data to SMEM.
    #pragma unroll
    for (int it = 0; it < 4; ++it) {
        if (dsts[it] >= 0) {
            float* dst = &tile[dsts[it]];
            dst[0] = v[it].x; dst[1] = v[it].y;
            dst[2] = v[it].z; dst[3] = v[it].w;
        }
    }
    __syncthreads();

    // ---- Store phase: identical to best (96.1us) ----
    #pragma unroll 1
    for (int g = tid; g < NGROUPS; g += NTHREADS) {
        const int oh  = g / 14;
        const int ow4 = (g - oh * 14) * 4;          // 0,4,...,52

        const int cbase = (oh + 3) * TPITCH + ow4 + 3;
        const float c0 = tile[cbase + 0];
        const float c1 = tile[cbase + 1];
        const float c2 = tile[cbase + 2];
        const float c3 = tile[cbase + 3];

        float* __restrict__ op = outb + 4 * g;

        #pragma unroll
        for (int i = 0; i < 7; ++i) {
            const float4* rp =
                reinterpret_cast<const float4*>(&tile[(oh + i) * TPITCH + ow4]);
            const float4 a = rp[0];
            const float4 b = rp[1];
            const float4 cq = rp[2];
            const float r[12] = {a.x, a.y, a.z, a.w,
                                 b.x, b.y, b.z, b.w,
                                 cq.x, cq.y, cq.z, cq.w};
            #pragma unroll
            for (int j = 0; j < 7; ++j) {
                float4 o;
                o.x = c0 - r[j + 0];
                o.y = c1 - r[j + 1];
                o.z = c2 - r[j + 2];
                o.w = c3 - r[j + 3];
                __stcs(reinterpret_cast<float4*>(op + (i * 7 + j) * PLANE), o);
            }
        }
    }
}

extern "C" void kernel_launch(void* const* d_in, const int* in_sizes, int n_in,
                              void* d_out, int out_size) {
    const float* x = (const float*)d_in[0];
    float* out = (float*)d_out;
    Subtraction_68212670595965_kernel<<<1024, NTHREADS>>>(x, out);
}